// round 2
// baseline (speedup 1.0000x reference)
#include <cuda_runtime.h>

#define CCH 256
#define CMID 16
#define HWSZ 16384
#define NGRP 32

// ---- device scratch (no allocations) ----
__device__ float g_dw[201326592];   // [(proj*2+input)][b][c][hw] proj:0=q,1=k,2=v
__device__ float g_q[4194304];      // [input][b][m][hw]
__device__ float g_k[4194304];
__device__ float g_fused[33554432]; // [b][c][hw]
__device__ float g_psum[131072];    // [b][g][blk][2]
__device__ float2 g_stats[256];     // [b][g]

// ---- K1: fused depthwise 3x3 (q,k,v) on both inputs ----
__global__ __launch_bounds__(256) void dw_kernel(
    const float* __restrict__ img, const float* __restrict__ mask,
    const float* __restrict__ qw, const float* __restrict__ qb,
    const float* __restrict__ kw, const float* __restrict__ kb,
    const float* __restrict__ vw, const float* __restrict__ vb)
{
    int bid = blockIdx.x;
    int band = bid & 15;
    int bc = (bid >> 4) & 2047;
    int input = bid >> 15;
    int c = bc & 255;
    const float* src = (input ? mask : img) + (size_t)bc * HWSZ;

    __shared__ float s[10 * 132];
    int t = threadIdx.x;
    int y0 = band * 8;
    for (int i = t; i < 10 * 130; i += 256) {
        int r = i / 130, cc = i - r * 130;
        int gy = y0 - 1 + r, gx = cc - 1;
        float v = 0.f;
        if ((unsigned)gy < 128u && (unsigned)gx < 128u) v = src[gy * 128 + gx];
        s[r * 132 + cc] = v;
    }
    float wq[9], wk[9], wv[9];
#pragma unroll
    for (int j = 0; j < 9; j++) { wq[j]=qw[c*9+j]; wk[j]=kw[c*9+j]; wv[j]=vw[c*9+j]; }
    float bq = qb[c], bk = kb[c], bv = vb[c];
    __syncthreads();

    int x = t & 127, quad = t >> 7;
    float aq[4], ak[4], av[4];
#pragma unroll
    for (int r = 0; r < 4; r++) { aq[r]=bq; ak[r]=bk; av[r]=bv; }
#pragma unroll
    for (int dx = 0; dx < 3; dx++) {
        float col[6];
#pragma unroll
        for (int rr = 0; rr < 6; rr++) col[rr] = s[(quad*4+rr)*132 + x + dx];
#pragma unroll
        for (int r = 0; r < 4; r++)
#pragma unroll
            for (int dy = 0; dy < 3; dy++) {
                float v = col[r + dy]; int j = dy*3 + dx;
                aq[r] += wq[j]*v; ak[r] += wk[j]*v; av[r] += wv[j]*v;
            }
    }
    float* dq = g_dw + ((size_t)(0 + input)*2048 + bc)*(size_t)HWSZ;
    float* dk = g_dw + ((size_t)(2 + input)*2048 + bc)*(size_t)HWSZ;
    float* dv = g_dw + ((size_t)(4 + input)*2048 + bc)*(size_t)HWSZ;
#pragma unroll
    for (int r = 0; r < 4; r++) {
        int y = y0 + quad*4 + r;
        dq[y*128 + x] = aq[r]; dk[y*128 + x] = ak[r]; dv[y*128 + x] = av[r];
    }
}

// ---- K2: q/k pointwise (16x256 per pixel) ----
__global__ __launch_bounds__(256) void pwqk_kernel(
    const float* __restrict__ qpw_w, const float* __restrict__ qpw_b,
    const float* __restrict__ kpw_w, const float* __restrict__ kpw_b)
{
    int which = blockIdx.y;          // 0:q-img 1:q-mask 2:k-img 3:k-mask
    int input = which & 1, proj = which >> 1;
    const float* Wp = proj ? kpw_w : qpw_w;
    const float* bp = proj ? kpw_b : qpw_b;
    const float* dwb = g_dw + (size_t)(proj*2 + input)*2048*(size_t)HWSZ;
    float* outb = (proj ? g_k : g_q) + (size_t)input*8*CMID*HWSZ;

    __shared__ float4 ws[CMID*64];
    __shared__ float  bs[CMID];
    int t = threadIdx.x;
    for (int i = t; i < CMID*64; i += 256) ws[i] = ((const float4*)Wp)[i];
    if (t < CMID) bs[t] = bp[t];
    __syncthreads();

    int n = blockIdx.x*256 + t;
    int b = n >> 14, hw = n & 16383;
    const float* xp = dwb + ((size_t)b*CCH)*HWSZ + hw;
    float acc[CMID];
#pragma unroll
    for (int m = 0; m < CMID; m++) acc[m] = bs[m];
#pragma unroll 4
    for (int c4 = 0; c4 < 64; c4++) {
        float x0 = xp[(size_t)(4*c4+0)*HWSZ];
        float x1 = xp[(size_t)(4*c4+1)*HWSZ];
        float x2 = xp[(size_t)(4*c4+2)*HWSZ];
        float x3 = xp[(size_t)(4*c4+3)*HWSZ];
#pragma unroll
        for (int m = 0; m < CMID; m++) {
            float4 w = ws[m*64 + c4];
            acc[m] += w.x*x0 + w.y*x1 + w.z*x2 + w.w*x3;
        }
    }
    float* op = outb + ((size_t)b*CMID)*HWSZ + hw;
#pragma unroll
    for (int m = 0; m < CMID; m++) op[(size_t)m*HWSZ] = acc[m];
}

// ---- K3 helpers ----
__device__ __forceinline__ void qk_gemm(const float* sQ, const float* sK, float* sSt, int t)
{
    int tx = t & 15, ty = t >> 4;
    int q0 = tx*4, p0 = ty*4;
    float a[4][4];
#pragma unroll
    for (int i=0;i<4;i++)
#pragma unroll
        for (int j=0;j<4;j++) a[i][j]=0.f;
#pragma unroll
    for (int c = 0; c < 16; c++) {
        float4 kk = *(const float4*)&sK[c*64 + q0];
        float4 qq = *(const float4*)&sQ[c*64 + p0];
        float kr[4]={kk.x,kk.y,kk.z,kk.w}, qr[4]={qq.x,qq.y,qq.z,qq.w};
#pragma unroll
        for (int i=0;i<4;i++)
#pragma unroll
            for (int j=0;j<4;j++) a[i][j] += kr[i]*qr[j];
    }
#pragma unroll
    for (int i=0;i<4;i++)
#pragma unroll
        for (int j=0;j<4;j++) sSt[(q0+i)*68 + p0+j] = 0.25f*a[i][j];
}

__device__ __forceinline__ void softmax_col(float* sSt, int p, float scale)
{
    float mx = -1e30f;
    for (int q = 0; q < 64; q++) mx = fmaxf(mx, sSt[q*68+p]);
    float sum = 0.f;
    for (int q = 0; q < 64; q++) { float e = __expf(sSt[q*68+p]-mx); sSt[q*68+p]=e; sum+=e; }
    float inv = scale / sum;
    for (int q = 0; q < 64; q++) sSt[q*68+p] *= inv;
}

__device__ __forceinline__ void t_accum(float acc[8][8], const float* sV, const float* sSt,
                                        int c0, int p0)
{
#pragma unroll 2
    for (int q = 0; q < 64; q++) {
        float av[8];
#pragma unroll
        for (int i=0;i<8;i++) av[i] = sV[(c0+i)*65 + q];
        float4 u0 = *(const float4*)&sSt[q*68 + p0];
        float4 u1 = *(const float4*)&sSt[q*68 + p0 + 4];
        float uu[8]={u0.x,u0.y,u0.z,u0.w,u1.x,u1.y,u1.z,u1.w};
#pragma unroll
        for (int i=0;i<8;i++)
#pragma unroll
            for (int j=0;j<8;j++) acc[i][j] += av[i]*uu[j];
    }
}

// smem layout (floats): Q 0..1024, K 1024..2048, St1 2048(4352), St2 6400(4352),
// V/U union 10752(17408), W 28160(4160)  -> 32320 floats = 129280 B
#define SMEM_FLOATS 32320

// ---- K3: attention both directions + Wv GEMM + residual + GN partials ----
__global__ __launch_bounds__(256, 1) void attn_kernel(
    const float* __restrict__ img, const float* __restrict__ mask,
    const float* __restrict__ vpw_w, const float* __restrict__ vpw_b,
    const float* __restrict__ alpha_p, const float* __restrict__ beta_p)
{
    extern __shared__ float sm[];
    float* sQ   = sm;
    float* sK   = sm + 1024;
    float* sSt1 = sm + 2048;
    float* sSt2 = sm + 6400;
    float* sV   = sm + 10752;   // stride 65, also reused as sU (stride 68)
    float* sU   = sm + 10752;
    float* sW   = sm + 28160;   // 16 x 260

    int t = threadIdx.x;
    int bid = blockIdx.x;
    int b = bid >> 8, blkid = bid & 255;
    int by = blkid >> 4, bx = blkid & 15;
    float al = __ldg(alpha_p), be = __ldg(beta_p);
    int hw00 = by*8*128 + bx*8;

    // dir1: Q=mask, K=img
    {
        const float* qs = g_q + (((size_t)8 + b)*CMID)*HWSZ;
        const float* ks = g_k + (((size_t)0 + b)*CMID)*HWSZ;
        for (int e = t; e < 1024; e += 256) {
            int m = e >> 6, p = e & 63;
            int hw = hw00 + ((p>>3)<<7) + (p&7);
            sQ[m*64+p] = qs[(size_t)m*HWSZ + hw];
            sK[m*64+p] = ks[(size_t)m*HWSZ + hw];
        }
    }
    __syncthreads();
    qk_gemm(sQ, sK, sSt1, t);
    __syncthreads();
    // dir2 load + softmax(St1, alpha)
    {
        const float* qs = g_q + (((size_t)0 + b)*CMID)*HWSZ;
        const float* ks = g_k + (((size_t)8 + b)*CMID)*HWSZ;
        for (int e = t; e < 1024; e += 256) {
            int m = e >> 6, p = e & 63;
            int hw = hw00 + ((p>>3)<<7) + (p&7);
            sQ[m*64+p] = qs[(size_t)m*HWSZ + hw];
            sK[m*64+p] = ks[(size_t)m*HWSZ + hw];
        }
        if (t < 64) softmax_col(sSt1, t, al);
    }
    __syncthreads();
    qk_gemm(sQ, sK, sSt2, t);
    __syncthreads();
    // load dwv(img) + softmax(St2, beta)
    {
        const float* vs = g_dw + (((size_t)4*8 + b)*CCH)*(size_t)HWSZ;
        for (int e = t; e < 256*64; e += 256) {
            int c = e >> 6, q = e & 63;
            int hw = hw00 + ((q>>3)<<7) + (q&7);
            sV[c*65+q] = vs[(size_t)c*HWSZ + hw];
        }
        if (t < 64) softmax_col(sSt2, t, be);
    }
    __syncthreads();

    int pg = t & 7, cg = t >> 3;
    int c0 = cg*8, p0 = pg*8;
    float acc[8][8];
#pragma unroll
    for (int i=0;i<8;i++)
#pragma unroll
        for (int j=0;j<8;j++) acc[i][j]=0.f;

    t_accum(acc, sV, sSt1, c0, p0);     // alpha folded in St1
    __syncthreads();
    {
        const float* vs = g_dw + (((size_t)5*8 + b)*CCH)*(size_t)HWSZ;
        for (int e = t; e < 256*64; e += 256) {
            int c = e >> 6, q = e & 63;
            int hw = hw00 + ((q>>3)<<7) + (q&7);
            sV[c*65+q] = vs[(size_t)c*HWSZ + hw];
        }
    }
    __syncthreads();
    t_accum(acc, sV, sSt2, c0, p0);     // beta folded in St2
    __syncthreads();
    // spill U (overwrites sV region)
#pragma unroll
    for (int i = 0; i < 8; i++) {
        *(float4*)&sU[(c0+i)*68 + p0]     = make_float4(acc[i][0],acc[i][1],acc[i][2],acc[i][3]);
        *(float4*)&sU[(c0+i)*68 + p0 + 4] = make_float4(acc[i][4],acc[i][5],acc[i][6],acc[i][7]);
    }
    __syncthreads();

    // fused = Wv * U + (al+be)*bv
    float ab = al + be;
#pragma unroll
    for (int i = 0; i < 8; i++) {
        float bv = vpw_b[c0+i];
#pragma unroll
        for (int j = 0; j < 8; j++) acc[i][j] = ab*bv;
    }
    for (int kc = 0; kc < 256; kc += 16) {
        for (int e = t; e < 4096; e += 256) {
            int o = e >> 4, cx = e & 15;
            sW[cx*260 + o] = vpw_w[o*256 + kc + cx];
        }
        __syncthreads();
#pragma unroll
        for (int cx = 0; cx < 16; cx++) {
            float4 w0 = *(const float4*)&sW[cx*260 + c0];
            float4 w1 = *(const float4*)&sW[cx*260 + c0 + 4];
            float4 u0 = *(const float4*)&sU[(kc+cx)*68 + p0];
            float4 u1 = *(const float4*)&sU[(kc+cx)*68 + p0 + 4];
            float wr[8]={w0.x,w0.y,w0.z,w0.w,w1.x,w1.y,w1.z,w1.w};
            float ur[8]={u0.x,u0.y,u0.z,u0.w,u1.x,u1.y,u1.z,u1.w};
#pragma unroll
            for (int i=0;i<8;i++)
#pragma unroll
                for (int j=0;j<8;j++) acc[i][j] += wr[i]*ur[j];
        }
        __syncthreads();
    }

    // epilogue: + img + mask, write fused, GN partial sums (deterministic)
    float lsum = 0.f, lsq = 0.f;
    size_t gb0 = (((size_t)b*CCH + c0) << 14) + (size_t)hw00 + ((size_t)pg << 7);
#pragma unroll
    for (int i = 0; i < 8; i++) {
        size_t ga = gb0 + ((size_t)i << 14);
        float4 i0 = *(const float4*)&img[ga];
        float4 i1 = *(const float4*)&img[ga+4];
        float4 m0 = *(const float4*)&mask[ga];
        float4 m1 = *(const float4*)&mask[ga+4];
        float4 r0, r1;
        r0.x=acc[i][0]+i0.x+m0.x; r0.y=acc[i][1]+i0.y+m0.y;
        r0.z=acc[i][2]+i0.z+m0.z; r0.w=acc[i][3]+i0.w+m0.w;
        r1.x=acc[i][4]+i1.x+m1.x; r1.y=acc[i][5]+i1.y+m1.y;
        r1.z=acc[i][6]+i1.z+m1.z; r1.w=acc[i][7]+i1.w+m1.w;
        *(float4*)&g_fused[ga]   = r0;
        *(float4*)&g_fused[ga+4] = r1;
        lsum += r0.x+r0.y+r0.z+r0.w + r1.x+r1.y+r1.z+r1.w;
        lsq  += r0.x*r0.x+r0.y*r0.y+r0.z*r0.z+r0.w*r0.w
              + r1.x*r1.x+r1.y*r1.y+r1.z*r1.z+r1.w*r1.w;
    }
#pragma unroll
    for (int off = 1; off < 8; off <<= 1) {
        lsum += __shfl_xor_sync(0xffffffffu, lsum, off);
        lsq  += __shfl_xor_sync(0xffffffffu, lsq, off);
    }
    if (pg == 0) {
        int idx = ((b*NGRP + cg)*256 + blkid)*2;
        g_psum[idx] = lsum; g_psum[idx+1] = lsq;
    }
}

// ---- K4: reduce GN partials ----
__global__ __launch_bounds__(256) void stats_kernel()
{
    int bg = blockIdx.x, t = threadIdx.x;
    float2 v = ((const float2*)g_psum)[bg*256 + t];
    float s = v.x, q = v.y;
#pragma unroll
    for (int o = 16; o; o >>= 1) {
        s += __shfl_xor_sync(0xffffffffu, s, o);
        q += __shfl_xor_sync(0xffffffffu, q, o);
    }
    __shared__ float ss[8], qs[8];
    if ((t & 31) == 0) { ss[t>>5] = s; qs[t>>5] = q; }
    __syncthreads();
    if (t == 0) {
        for (int w = 1; w < 8; w++) { s += ss[w]; q += qs[w]; }
        float inv = 1.f / 131072.f;
        float mu = s * inv;
        float var = q * inv - mu*mu;
        g_stats[bg] = make_float2(mu, rsqrtf(var + 1e-5f));
    }
}

// ---- K5: normalize ----
__global__ __launch_bounds__(1024) void norm_kernel(
    float* __restrict__ out, const float* __restrict__ gamma, const float* __restrict__ beta)
{
    int i4 = blockIdx.x*1024 + threadIdx.x;
    size_t e = (size_t)i4 << 2;
    int b = (int)(e >> 22), c = (int)(e >> 14) & 255;
    float2 st = g_stats[b*32 + (c >> 3)];
    float gsc = gamma[c] * st.y;
    float bsh = beta[c] - st.x * gsc;
    float4 f = *(const float4*)&g_fused[e];
    float4 r;
    r.x = f.x*gsc + bsh; r.y = f.y*gsc + bsh;
    r.z = f.z*gsc + bsh; r.w = f.w*gsc + bsh;
    *(float4*)&out[e] = r;
}

extern "C" void kernel_launch(void* const* d_in, const int* in_sizes, int n_in,
                              void* d_out, int out_size)
{
    const float* img    = (const float*)d_in[0];
    const float* mask   = (const float*)d_in[1];
    const float* qdw_w  = (const float*)d_in[2];
    const float* qdw_b  = (const float*)d_in[3];
    const float* kdw_w  = (const float*)d_in[4];
    const float* kdw_b  = (const float*)d_in[5];
    const float* vdw_w  = (const float*)d_in[6];
    const float* vdw_b  = (const float*)d_in[7];
    const float* qpw_w  = (const float*)d_in[8];
    const float* qpw_b  = (const float*)d_in[9];
    const float* kpw_w  = (const float*)d_in[10];
    const float* kpw_b  = (const float*)d_in[11];
    const float* vpw_w  = (const float*)d_in[12];
    const float* vpw_b  = (const float*)d_in[13];
    const float* alpha  = (const float*)d_in[14];
    const float* beta   = (const float*)d_in[15];
    const float* gn_w   = (const float*)d_in[16];
    const float* gn_b   = (const float*)d_in[17];

    cudaFuncSetAttribute(attn_kernel, cudaFuncAttributeMaxDynamicSharedMemorySize,
                         SMEM_FLOATS * 4);

    dw_kernel<<<65536, 256>>>(img, mask, qdw_w, qdw_b, kdw_w, kdw_b, vdw_w, vdw_b);
    dim3 g2(512, 4);
    pwqk_kernel<<<g2, 256>>>(qpw_w, qpw_b, kpw_w, kpw_b);
    attn_kernel<<<2048, 256, SMEM_FLOATS * 4>>>(img, mask, vpw_w, vpw_b, alpha, beta);
    stats_kernel<<<256, 256>>>();
    norm_kernel<<<8192, 1024>>>((float*)d_out, gn_w, gn_b);
}